// round 13
// baseline (speedup 1.0000x reference)
#include <cuda_runtime.h>
#include <cuda_bf16.h>
#include <stdint.h>
#include <math.h>

// RecognitionODERNN: B=256, T=96, OBS=64, LATENT=256, HID=512, N_SUB=3
//
// 32 clusters x 4 CTAs = 128 CTAs, 512 thr/CTA, EIGHT batch rows per cluster
// (halves chip L2 weight traffic vs 4 rows). Rank r owns hid cols
// [r*128,+128) in phase A and K-rows [r*128,+128) in phase B. Phase-B
// partials all-reduced across the 4 CTAs by a 2-stage butterfly (rank^1,
// rank^2) over DSMEM, double-buffered, mbarrier release/acquire.
// Activations: packed row-pairs, 32B/entry (8 rows); inner-loop LDS are
// warp-uniform broadcasts. Weights LDG.64/LDG.128 from L2; fma.rn.f32x2.

#define TSEQ 96
#define OBSD 64
#define LAT  256
#define HIDD 512
#define KRNN 320
#define ROWS 8
#define TPB  512
#define NCTA 128
#define CLU  4
#define HQ   128      // hid cols per CTA (phase A)
#define KQ   128      // K rows per CTA (phase B)

typedef unsigned long long u64;
typedef unsigned int u32;

struct row8 { ulonglong2 a, b; };   // (r0,r1),(r2,r3),(r4,r5),(r6,r7)

__device__ __forceinline__ u64 pk2(float x, float y) {
    u64 r; asm("mov.b64 %0, {%1, %2};" : "=l"(r) : "f"(x), "f"(y)); return r;
}
__device__ __forceinline__ void up2(u64 p, float &x, float &y) {
    asm("mov.b64 {%0, %1}, %2;" : "=f"(x), "=f"(y) : "l"(p));
}
__device__ __forceinline__ u64 ffma2(u64 a, u64 b, u64 c) {
    u64 d; asm("fma.rn.f32x2 %0, %1, %2, %3;" : "=l"(d) : "l"(a), "l"(b), "l"(c));
    return d;
}
__device__ __forceinline__ u64 fadd2(u64 a, u64 b) {
    u64 d; asm("add.rn.f32x2 %0, %1, %2;" : "=l"(d) : "l"(a), "l"(b)); return d;
}

__device__ __forceinline__ u32 smem_u32(const void *p) {
    u32 a;
    asm("{ .reg .u64 t; cvta.to.shared.u64 t, %1; cvt.u32.u64 %0, t; }"
        : "=r"(a) : "l"(p));
    return a;
}
__device__ __forceinline__ u32 mapa32(u32 addr, u32 rank) {
    u32 r;
    asm("mapa.shared::cluster.u32 %0, %1, %2;" : "=r"(r) : "r"(addr), "r"(rank));
    return r;
}
__device__ __forceinline__ void st_remote32(u32 addr, const row8 &p) {
    asm volatile("st.shared::cluster.u64 [%0], %1;" :: "r"(addr),      "l"(p.a.x) : "memory");
    asm volatile("st.shared::cluster.u64 [%0], %1;" :: "r"(addr + 8),  "l"(p.a.y) : "memory");
    asm volatile("st.shared::cluster.u64 [%0], %1;" :: "r"(addr + 16), "l"(p.b.x) : "memory");
    asm volatile("st.shared::cluster.u64 [%0], %1;" :: "r"(addr + 24), "l"(p.b.y) : "memory");
}
__device__ __forceinline__ void arrive_remote(u32 rmbar) {
    asm volatile("mbarrier.arrive.release.cluster.shared::cluster.b64 _, [%0];"
                 :: "r"(rmbar) : "memory");
}
__device__ __forceinline__ void wait_parity_cluster(u32 mbar, u32 ph) {
    asm volatile(
        "{\n\t"
        ".reg .pred P;\n"
        "WLOOP%=:\n\t"
        "mbarrier.try_wait.parity.acquire.cluster.shared::cta.b64 P, [%0], %1;\n\t"
        "@!P bra WLOOP%=;\n\t"
        "}"
        :: "r"(mbar), "r"(ph) : "memory");
}
__device__ __forceinline__ void cluster_sync() {
    asm volatile("barrier.cluster.arrive.aligned;" ::: "memory");
    asm volatile("barrier.cluster.wait.aligned;" ::: "memory");
}

__device__ __forceinline__ void racc(row8 &d, const row8 &s) {
    d.a.x = fadd2(d.a.x, s.a.x); d.a.y = fadd2(d.a.y, s.a.y);
    d.b.x = fadd2(d.b.x, s.b.x); d.b.y = fadd2(d.b.y, s.b.y);
}

// ---------------------------------------------------------------------------
// Phase A: 2 cols/thread over K-slice sA (8 slices of KS rows); W stride HIDD.
// All inner LDS are warp-uniform broadcasts (sA constant per warp).
// ---------------------------------------------------------------------------
template <int KS>
__device__ __forceinline__ void gemmA(const row8 *__restrict__ in,
                                      const float *__restrict__ W,
                                      row8 *__restrict__ sPart, int sA, int cA)
{
    const row8 *ip = in + sA * KS;
    const float *wp = W + (size_t)(sA * KS) * HIDD + cA;
    u64 p00 = 0, p01 = 0, p02 = 0, p03 = 0;   // col cA,   4 row-pairs
    u64 p10 = 0, p11 = 0, p12 = 0, p13 = 0;   // col cA+1
#pragma unroll 4
    for (int k = 0; k < KS; ++k) {
        row8 v = ip[k];
        float2 w = *reinterpret_cast<const float2 *>(wp + (size_t)k * HIDD);
        u64 W0 = pk2(w.x, w.x), W1 = pk2(w.y, w.y);
        p00 = ffma2(v.a.x, W0, p00); p01 = ffma2(v.a.y, W0, p01);
        p02 = ffma2(v.b.x, W0, p02); p03 = ffma2(v.b.y, W0, p03);
        p10 = ffma2(v.a.x, W1, p10); p11 = ffma2(v.a.y, W1, p11);
        p12 = ffma2(v.b.x, W1, p12); p13 = ffma2(v.b.y, W1, p13);
    }
    row8 o;
    o.a.x = p00; o.a.y = p01; o.b.x = p02; o.b.y = p03; sPart[sA * HQ + cA]     = o;
    o.a.x = p10; o.a.y = p11; o.b.x = p12; o.b.y = p13; sPart[sA * HQ + cA + 1] = o;
}

// ---------------------------------------------------------------------------
// Phase B: 2 cols/thread over K-slice sB (4 slices of 32 rows); W stride LAT.
// ---------------------------------------------------------------------------
__device__ __forceinline__ void gemmB(const row8 *__restrict__ hid,
                                      const float *__restrict__ W,
                                      row8 *__restrict__ sPart, int sB, int cB)
{
    const int KS = KQ / 4;   // 32
    const row8 *ip = hid + sB * KS;
    const float *wp = W + (size_t)(sB * KS) * LAT + cB;
    u64 p00 = 0, p01 = 0, p02 = 0, p03 = 0;
    u64 p10 = 0, p11 = 0, p12 = 0, p13 = 0;
#pragma unroll 4
    for (int k = 0; k < KS; ++k) {
        row8 v = ip[k];
        float2 w = *reinterpret_cast<const float2 *>(wp + (size_t)k * LAT);
        u64 W0 = pk2(w.x, w.x), W1 = pk2(w.y, w.y);
        p00 = ffma2(v.a.x, W0, p00); p01 = ffma2(v.a.y, W0, p01);
        p02 = ffma2(v.b.x, W0, p02); p03 = ffma2(v.b.y, W0, p03);
        p10 = ffma2(v.a.x, W1, p10); p11 = ffma2(v.a.y, W1, p11);
        p12 = ffma2(v.b.x, W1, p12); p13 = ffma2(v.b.y, W1, p13);
    }
    row8 o;
    o.a.x = p00; o.a.y = p01; o.b.x = p02; o.b.y = p03; sPart[sB * LAT + cB]     = o;
    o.a.x = p10; o.a.y = p11; o.b.x = p12; o.b.y = p13; sPart[sB * LAT + cB + 1] = o;
}

// ---------------------------------------------------------------------------
// One full MLP eval with 4-way butterfly all-reduce on phase B.
// Returns out column t (8 rows) for t < LAT; zeros otherwise.
// ---------------------------------------------------------------------------
template <int KSA>
__device__ __forceinline__ row8 mlp_eval(
    const row8 *__restrict__ in,
    const float *__restrict__ Wa, float ba,
    const float *__restrict__ Wb, float bb,
    row8 *__restrict__ sHid, row8 *__restrict__ sPart,
    row8 *__restrict__ sX1, row8 *__restrict__ sX2,
    u32 peer1Buf, u32 my1, u32 peer1,
    u32 peer2Buf, u32 my2, u32 peer2,
    int t, int sA, int cA, int sB, int cB, int &x)
{
    gemmA<KSA>(in, Wa, sPart, sA, cA);
    __syncthreads();
    if (t < HQ) {   // combine 8 slices + bias + tanh -> local hid quarter
        row8 h = sPart[t];
#pragma unroll
        for (int s2 = 1; s2 < 8; ++s2) racc(h, sPart[s2 * HQ + t]);
        u64 bp = pk2(ba, ba);
        h.a.x = fadd2(h.a.x, bp); h.a.y = fadd2(h.a.y, bp);
        h.b.x = fadd2(h.b.x, bp); h.b.y = fadd2(h.b.y, bp);
        float u0, u1, u2, u3, u4, u5, u6, u7;
        up2(h.a.x, u0, u1); up2(h.a.y, u2, u3);
        up2(h.b.x, u4, u5); up2(h.b.y, u6, u7);
        row8 th;
        th.a.x = pk2(tanhf(u0), tanhf(u1)); th.a.y = pk2(tanhf(u2), tanhf(u3));
        th.b.x = pk2(tanhf(u4), tanhf(u5)); th.b.y = pk2(tanhf(u6), tanhf(u7));
        sHid[t] = th;
    }
    __syncthreads();
    gemmB(sHid, Wb, sPart, sB, cB);
    __syncthreads();

    row8 p; p.a.x = 0; p.a.y = 0; p.b.x = 0; p.b.y = 0;
    const int buf = x & 1;
    if (t < LAT) {
        p = sPart[t];
#pragma unroll
        for (int s2 = 1; s2 < 4; ++s2) racc(p, sPart[s2 * LAT + t]);
        // butterfly stage 1: rank ^ 1
        st_remote32(peer1Buf + (u32)(buf * LAT + t) * 32u, p);
        arrive_remote(peer1);
        wait_parity_cluster(my1, (u32)buf);
        racc(p, sX1[buf * LAT + t]);
        // butterfly stage 2: rank ^ 2
        st_remote32(peer2Buf + (u32)(buf * LAT + t) * 32u, p);
        arrive_remote(peer2);
        wait_parity_cluster(my2, (u32)buf);
        racc(p, sX2[buf * LAT + t]);
        u64 bp = pk2(bb, bb);
        p.a.x = fadd2(p.a.x, bp); p.a.y = fadd2(p.a.y, bp);
        p.b.x = fadd2(p.b.x, bp); p.b.y = fadd2(p.b.y, bp);
    }
    x++;
    return p;
}

// ---------------------------------------------------------------------------
__global__ void __launch_bounds__(TPB, 1) __cluster_dims__(CLU, 1, 1)
odernn_kernel(const float *__restrict__ dataset,    // [B, T, OBS]
              const float *__restrict__ timestamps, // [B, T]
              const float *__restrict__ W1,  const float *__restrict__ b1,
              const float *__restrict__ W2,  const float *__restrict__ b2,
              const float *__restrict__ Wr1, const float *__restrict__ br1,
              const float *__restrict__ Wr2, const float *__restrict__ br2,
              float *__restrict__ out)               // [B, LAT]
{
    extern __shared__ char smem[];
    row8  *sC    = reinterpret_cast<row8 *>(smem);     // [320] state+obs
    row8  *sTmp  = sC + KRNN;                          // [256] RK4 eval point
    row8  *sKA   = sTmp + LAT;                         // [256] RK4 k-accum
    row8  *sHid  = sKA + LAT;                          // [128] local hid quarter
    row8  *sPart = sHid + HQ;                          // [1024] (8*128 == 4*256)
    row8  *sX1   = sPart + 1024;                       // [2*256] stage-1 recv
    row8  *sX2   = sX1 + 512;                          // [2*256] stage-2 recv
    float *sH    = reinterpret_cast<float *>(sX2 + 512);  // [8]
    float *sQ    = sH + 8;                             // [8]
    float *sG    = sQ + 8;                             // [8]
    u64   *mb    = reinterpret_cast<u64 *>(sG + 8);    // [2]

    const int t = threadIdx.x;
    u32 rank;
    asm("mov.u32 %0, %%cluster_ctarank;" : "=r"(rank));
    const int row0  = (blockIdx.x / CLU) * ROWS;
    const int hbase = (int)rank * HQ;

    const int sA = t >> 6, cA = 2 * (t & 63);     // phase A: 8 slices x 64 grp
    const int sB = t >> 7, cB = 2 * (t & 127);    // phase B: 4 slices x 128 grp

    const u32 my1      = smem_u32(mb);
    const u32 my2      = smem_u32(mb + 1);
    const u32 peer1    = mapa32(my1, rank ^ 1u);
    const u32 peer2    = mapa32(my2, rank ^ 2u);
    const u32 peer1Buf = mapa32(smem_u32(sX1), rank ^ 1u);
    const u32 peer2Buf = mapa32(smem_u32(sX2), rank ^ 2u);

    // weight slices for this rank
    const float *W1r  = W1  + hbase;                    // phase-A cols
    const float *Wr1r = Wr1 + hbase;
    const float *W2r  = W2  + (size_t)hbase * LAT;      // phase-B K-rows
    const float *Wr2r = Wr2 + (size_t)hbase * LAT;

    const float baO = (t < HQ) ? b1[hbase + t]   : 0.f;
    const float baR = (t < HQ) ? br1[hbase + t]  : 0.f;
    const float bbO = (t < LAT) ? b2[t]  : 0.f;
    const float bbR = (t < LAT) ? br2[t] : 0.f;

    // ---- init: mbars, state = 0, x_{T-1} ----
    if (t == 0) {
        asm volatile("mbarrier.init.shared.b64 [%0], %1;"
                     :: "r"(my1), "r"(LAT) : "memory");
        asm volatile("mbarrier.init.shared.b64 [%0], %1;"
                     :: "r"(my2), "r"(LAT) : "memory");
    }
    if (t < LAT) {
        row8 z; z.a.x = 0; z.a.y = 0; z.b.x = 0; z.b.y = 0;
        sC[t] = z;
    }
    {   // obs: 64 cols x 8 rows, one float per thread
        const int cc = t & (OBSD - 1);
        const int r  = t >> 6;
        float v = dataset[((row0 + r) * TSEQ + (TSEQ - 1)) * OBSD + cc];
        reinterpret_cast<float *>(&sC[LAT + cc])[r] = v;
    }
    __syncthreads();
    cluster_sync();    // mbars + state visible cluster-wide

    int x = 0;         // exchange counter

    // ---- initial RNN update: s += rnn(concat(s, x_{T-1})) ----
    {
        row8 o = mlp_eval<KRNN / 8>(sC, Wr1r, baR, Wr2r, bbR,
                                    sHid, sPart, sX1, sX2,
                                    peer1Buf, my1, peer1, peer2Buf, my2, peer2,
                                    t, sA, cA, sB, cB, x);
        if (t < LAT) { row8 d = sC[t]; racc(d, o); sC[t] = d; }
        __syncthreads();
    }

    // ---- reverse-time scan: i = T-2 .. 0 ----
    for (int i = TSEQ - 2; i >= 0; --i) {
        {
            const int cc = t & (OBSD - 1);
            const int r  = t >> 6;
            float v = dataset[((row0 + r) * TSEQ + i) * OBSD + cc];
            reinterpret_cast<float *>(&sC[LAT + cc])[r] = v;
        }
        if (t < ROWS) {
            const float *tsr = timestamps + (row0 + t) * TSEQ;
            float h = (tsr[i] - tsr[i + 1]) / 3.0f;
            sH[t] = h; sQ[t] = 0.5f * h; sG[t] = h / 6.0f;
        }
        __syncthreads();

#pragma unroll 1
        for (int sub = 0; sub < 3; ++sub) {
            // k1
            row8 k = mlp_eval<LAT / 8>(sC, W1r, baO, W2r, bbO,
                                       sHid, sPart, sX1, sX2,
                                       peer1Buf, my1, peer1, peer2Buf, my2, peer2,
                                       t, sA, cA, sB, cB, x);
            if (t < LAT) {
                sKA[t] = k;
                row8 sv = sC[t];
                u64 q01 = pk2(sQ[0], sQ[1]), q23 = pk2(sQ[2], sQ[3]);
                u64 q45 = pk2(sQ[4], sQ[5]), q67 = pk2(sQ[6], sQ[7]);
                row8 tv;
                tv.a.x = ffma2(k.a.x, q01, sv.a.x); tv.a.y = ffma2(k.a.y, q23, sv.a.y);
                tv.b.x = ffma2(k.b.x, q45, sv.b.x); tv.b.y = ffma2(k.b.y, q67, sv.b.y);
                sTmp[t] = tv;
            }
            __syncthreads();

            // k2
            k = mlp_eval<LAT / 8>(sTmp, W1r, baO, W2r, bbO,
                                  sHid, sPart, sX1, sX2,
                                  peer1Buf, my1, peer1, peer2Buf, my2, peer2,
                                  t, sA, cA, sB, cB, x);
            if (t < LAT) {
                row8 kk; kk.a.x = fadd2(k.a.x, k.a.x); kk.a.y = fadd2(k.a.y, k.a.y);
                kk.b.x = fadd2(k.b.x, k.b.x); kk.b.y = fadd2(k.b.y, k.b.y);
                row8 a = sKA[t]; racc(a, kk); sKA[t] = a;
                row8 sv = sC[t];
                u64 q01 = pk2(sQ[0], sQ[1]), q23 = pk2(sQ[2], sQ[3]);
                u64 q45 = pk2(sQ[4], sQ[5]), q67 = pk2(sQ[6], sQ[7]);
                row8 tv;
                tv.a.x = ffma2(k.a.x, q01, sv.a.x); tv.a.y = ffma2(k.a.y, q23, sv.a.y);
                tv.b.x = ffma2(k.b.x, q45, sv.b.x); tv.b.y = ffma2(k.b.y, q67, sv.b.y);
                sTmp[t] = tv;
            }
            __syncthreads();

            // k3
            k = mlp_eval<LAT / 8>(sTmp, W1r, baO, W2r, bbO,
                                  sHid, sPart, sX1, sX2,
                                  peer1Buf, my1, peer1, peer2Buf, my2, peer2,
                                  t, sA, cA, sB, cB, x);
            if (t < LAT) {
                row8 kk; kk.a.x = fadd2(k.a.x, k.a.x); kk.a.y = fadd2(k.a.y, k.a.y);
                kk.b.x = fadd2(k.b.x, k.b.x); kk.b.y = fadd2(k.b.y, k.b.y);
                row8 a = sKA[t]; racc(a, kk); sKA[t] = a;
                row8 sv = sC[t];
                u64 h01 = pk2(sH[0], sH[1]), h23 = pk2(sH[2], sH[3]);
                u64 h45 = pk2(sH[4], sH[5]), h67 = pk2(sH[6], sH[7]);
                row8 tv;
                tv.a.x = ffma2(k.a.x, h01, sv.a.x); tv.a.y = ffma2(k.a.y, h23, sv.a.y);
                tv.b.x = ffma2(k.b.x, h45, sv.b.x); tv.b.y = ffma2(k.b.y, h67, sv.b.y);
                sTmp[t] = tv;
            }
            __syncthreads();

            // k4 + state update
            k = mlp_eval<LAT / 8>(sTmp, W1r, baO, W2r, bbO,
                                  sHid, sPart, sX1, sX2,
                                  peer1Buf, my1, peer1, peer2Buf, my2, peer2,
                                  t, sA, cA, sB, cB, x);
            if (t < LAT) {
                row8 a = sKA[t]; racc(a, k);
                row8 sv = sC[t];
                u64 g01 = pk2(sG[0], sG[1]), g23 = pk2(sG[2], sG[3]);
                u64 g45 = pk2(sG[4], sG[5]), g67 = pk2(sG[6], sG[7]);
                row8 nv;
                nv.a.x = ffma2(a.a.x, g01, sv.a.x); nv.a.y = ffma2(a.a.y, g23, sv.a.y);
                nv.b.x = ffma2(a.b.x, g45, sv.b.x); nv.b.y = ffma2(a.b.y, g67, sv.b.y);
                sC[t] = nv;
            }
            __syncthreads();
        }

        // ---- RNN update: s += rnn(concat(s, x_i)) ----
        {
            row8 o = mlp_eval<KRNN / 8>(sC, Wr1r, baR, Wr2r, bbR,
                                        sHid, sPart, sX1, sX2,
                                        peer1Buf, my1, peer1, peer2Buf, my2, peer2,
                                        t, sA, cA, sB, cB, x);
            if (t < LAT) { row8 d = sC[t]; racc(d, o); sC[t] = d; }
            __syncthreads();
        }
    }

    // ---- write final state (rank 0 of each cluster; all ranks identical) ----
    if (rank == 0 && t < LAT) {
        row8 d = sC[t];
        float r0, r1, r2, r3, r4, r5, r6, r7;
        up2(d.a.x, r0, r1); up2(d.a.y, r2, r3);
        up2(d.b.x, r4, r5); up2(d.b.y, r6, r7);
        out[(row0 + 0) * LAT + t] = r0;
        out[(row0 + 1) * LAT + t] = r1;
        out[(row0 + 2) * LAT + t] = r2;
        out[(row0 + 3) * LAT + t] = r3;
        out[(row0 + 4) * LAT + t] = r4;
        out[(row0 + 5) * LAT + t] = r5;
        out[(row0 + 6) * LAT + t] = r6;
        out[(row0 + 7) * LAT + t] = r7;
    }

    cluster_sync();   // no CTA exits while peer traffic may be in flight
}

// ---------------------------------------------------------------------------
extern "C" void kernel_launch(void* const* d_in, const int* in_sizes, int n_in,
                              void* d_out, int out_size)
{
    (void)in_sizes; (void)n_in; (void)out_size;
    const float* dataset    = (const float*)d_in[0];
    const float* timestamps = (const float*)d_in[1];
    const float* W1  = (const float*)d_in[2];
    const float* b1  = (const float*)d_in[3];
    const float* W2  = (const float*)d_in[4];
    const float* b2  = (const float*)d_in[5];
    const float* Wr1 = (const float*)d_in[6];
    const float* br1 = (const float*)d_in[7];
    const float* Wr2 = (const float*)d_in[8];
    const float* br2 = (const float*)d_in[9];
    float* out = (float*)d_out;

    // row8 arrays: 320+256+256+128+1024+512+512 = 3008 entries * 32 B
    const size_t smem = 3008 * sizeof(row8)
                      + 24 * sizeof(float) + 2 * sizeof(u64) + 64;
    static int configured = 0;
    if (!configured) {
        cudaFuncSetAttribute(odernn_kernel,
                             cudaFuncAttributeMaxDynamicSharedMemorySize,
                             (int)smem);
        configured = 1;
    }
    odernn_kernel<<<NCTA, TPB, smem>>>(dataset, timestamps,
                                       W1, b1, W2, b2, Wr1, br1, Wr2, br2, out);
}

// round 14
// speedup vs baseline: 1.1497x; 1.1497x over previous
#include <cuda_runtime.h>
#include <cuda_bf16.h>
#include <stdint.h>
#include <math.h>

// RecognitionODERNN: B=256, T=96, OBS=64, LATENT=256, HID=512, N_SUB=3
//
// 2-CTA clusters x 64 = 128 CTAs, 1024 thr/CTA (8 warps/SMSP), 4 batch rows
// per cluster. Rank r owns hid cols [r*256,+256) (phase A) and K-rows
// [r*256,+256) (phase B); phase-B partials exchanged via DSMEM
// (double-buffered mbarrier release/acquire). Activations: packed row-pairs
// (ONE LDS.128 per k); weights LDG.64 (2 cols/thread, 8 slices x 128 groups);
// fma.rn.f32x2. Sized to fit the 64-reg ceiling at 1024 threads.

#define TSEQ  96
#define OBSD  64
#define LAT   256
#define HIDD  512
#define KRNN  320
#define ROWS  4
#define TPB   1024
#define NCTA  128
#define HHALF 256     // hid cols per CTA
#define NSL   8       // K slices per phase
#define NC    256     // output cols per phase per CTA

typedef unsigned long long u64;
typedef unsigned int u32;

__device__ __forceinline__ u64 pk2(float x, float y) {
    u64 r; asm("mov.b64 %0, {%1, %2};" : "=l"(r) : "f"(x), "f"(y)); return r;
}
__device__ __forceinline__ void up2(u64 p, float &x, float &y) {
    asm("mov.b64 {%0, %1}, %2;" : "=f"(x), "=f"(y) : "l"(p));
}
__device__ __forceinline__ u64 ffma2(u64 a, u64 b, u64 c) {
    u64 d; asm("fma.rn.f32x2 %0, %1, %2, %3;" : "=l"(d) : "l"(a), "l"(b), "l"(c));
    return d;
}
__device__ __forceinline__ u64 fadd2(u64 a, u64 b) {
    u64 d; asm("add.rn.f32x2 %0, %1, %2;" : "=l"(d) : "l"(a), "l"(b)); return d;
}

// fast, accurate-enough tanh: 1 - 2/(e^{2x}+1).  MUFU-based (~1e-7 rel err),
// saturates correctly for |x| large (exp->0 or inf).
__device__ __forceinline__ float tanh_fast(float x) {
    float e = __expf(2.0f * x);
    return 1.0f - __fdividef(2.0f, e + 1.0f);
}

__device__ __forceinline__ u32 smem_u32(const void *p) {
    u32 a;
    asm("{ .reg .u64 t; cvta.to.shared.u64 t, %1; cvt.u32.u64 %0, t; }"
        : "=r"(a) : "l"(p));
    return a;
}
__device__ __forceinline__ u32 mapa32(u32 addr, u32 rank) {
    u32 r;
    asm("mapa.shared::cluster.u32 %0, %1, %2;" : "=r"(r) : "r"(addr), "r"(rank));
    return r;
}
__device__ __forceinline__ void st_remote16(u32 addr, u64 x, u64 y) {
    asm volatile("st.shared::cluster.u64 [%0], %1;" :: "r"(addr), "l"(x) : "memory");
    asm volatile("st.shared::cluster.u64 [%0], %1;" :: "r"(addr + 8), "l"(y) : "memory");
}
__device__ __forceinline__ void arrive_remote(u32 rmbar) {
    asm volatile("mbarrier.arrive.release.cluster.shared::cluster.b64 _, [%0];"
                 :: "r"(rmbar) : "memory");
}
__device__ __forceinline__ void wait_parity_cluster(u32 mbar, u32 ph) {
    asm volatile(
        "{\n\t"
        ".reg .pred P;\n"
        "WLOOP%=:\n\t"
        "mbarrier.try_wait.parity.acquire.cluster.shared::cta.b64 P, [%0], %1;\n\t"
        "@!P bra WLOOP%=;\n\t"
        "}"
        :: "r"(mbar), "r"(ph) : "memory");
}
__device__ __forceinline__ void cluster_sync() {
    asm volatile("barrier.cluster.arrive.aligned;" ::: "memory");
    asm volatile("barrier.cluster.wait.aligned;" ::: "memory");
}

// store packed row-pairs (one STS.128)
__device__ __forceinline__ void store_p(ulonglong2 *dst, float v0, float v1,
                                        float v2, float v3)
{
    ulonglong2 d;
    d.x = pk2(v0, v1);
    d.y = pk2(v2, v3);
    *dst = d;
}

// ---------------------------------------------------------------------------
// thread computes 2 output columns [c0, c0+1] over K-slice s (KSPAN rows).
// per k: 1 LDS.128 (acts, broadcast) + 1 LDG.64 (2 weight cols) + 2 dup MOV
// + 4 FFMA2.  unroll 4 keeps live regs small (64-reg ceiling @1024 thr).
// ---------------------------------------------------------------------------
template <int KSPAN, int WSTRIDE>
__device__ __forceinline__ void gemm_slice(const ulonglong2 *__restrict__ in,
                                           const float *__restrict__ W,
                                           ulonglong2 *__restrict__ sPart,
                                           int s, int c0)
{
    const ulonglong2 *ip = in + s * KSPAN;
    const float *wp = W + (size_t)(s * KSPAN) * WSTRIDE + c0;

    u64 a00 = 0, a01 = 0;   // col c0  : (r0,r1), (r2,r3)
    u64 a10 = 0, a11 = 0;   // col c0+1
#pragma unroll 4
    for (int k = 0; k < KSPAN; ++k) {
        ulonglong2 a = ip[k];                      // LDS.128 broadcast
        float2 w = *reinterpret_cast<const float2 *>(wp + (size_t)k * WSTRIDE);
        u64 W0 = pk2(w.x, w.x), W1 = pk2(w.y, w.y);
        a00 = ffma2(a.x, W0, a00);  a01 = ffma2(a.y, W0, a01);
        a10 = ffma2(a.x, W1, a10);  a11 = ffma2(a.y, W1, a11);
    }
    ulonglong2 *base = sPart + s * NC;
    ulonglong2 v;
    v.x = a00; v.y = a01; base[c0]     = v;
    v.x = a10; v.y = a11; base[c0 + 1] = v;
}

// Sum 8 partial slices for column c (+ bias) -> ((r0,r1),(r2,r3))
__device__ __forceinline__ ulonglong2 combine8(const ulonglong2 *__restrict__ sPart,
                                               int c, float bias)
{
    ulonglong2 p0 = sPart[c];
    u64 sx = p0.x, sy = p0.y;
#pragma unroll
    for (int s = 1; s < NSL; ++s) {
        ulonglong2 p = sPart[s * NC + c];
        sx = fadd2(sx, p.x);
        sy = fadd2(sy, p.y);
    }
    u64 bb = pk2(bias, bias);
    ulonglong2 r; r.x = fadd2(sx, bb); r.y = fadd2(sy, bb);
    return r;
}

// ---------------------------------------------------------------------------
// One full MLP eval with cross-CTA K reduction on phase B.
// All TPB threads call this (contains barriers). Out valid for t < NC.
// ---------------------------------------------------------------------------
template <int KSA>
__device__ __forceinline__ float4 mlp_eval(
    const ulonglong2 *__restrict__ in,
    const float *__restrict__ Wa, float ba,
    const float *__restrict__ Wb, float bb,
    ulonglong2 *__restrict__ sHid, ulonglong2 *__restrict__ sPart,
    ulonglong2 *__restrict__ sPeer,
    u32 peerBufAddr, u32 mbarAddr, u32 mbarPeerAddr,
    int t, int s, int c0, int &x)
{
    gemm_slice<KSA, HIDD>(in, Wa, sPart, s, c0);
    __syncthreads();
    if (t < NC) {   // combine A + tanh -> local sHid (one hid col per thread)
        ulonglong2 h = combine8(sPart, t, ba);
        float u0, u1, u2, u3;
        up2(h.x, u0, u1); up2(h.y, u2, u3);
        store_p(&sHid[t], tanh_fast(u0), tanh_fast(u1),
                          tanh_fast(u2), tanh_fast(u3));
    }
    __syncthreads();
    gemm_slice<HHALF / NSL, LAT>(sHid, Wb, sPart, s, c0);
    __syncthreads();

    float4 res = make_float4(0.f, 0.f, 0.f, 0.f);
    const int buf = x & 1;
    if (t < NC) {
        ulonglong2 p = combine8(sPart, t, 0.f);          // local K-half partial
        st_remote16(peerBufAddr + (u32)(buf * NC + t) * 16u, p.x, p.y);
        arrive_remote(mbarPeerAddr);
        wait_parity_cluster(mbarAddr, (u32)buf);
        ulonglong2 q = sPeer[buf * NC + t];
        u64 bb2 = pk2(bb, bb);
        u64 sx = fadd2(fadd2(p.x, q.x), bb2);
        u64 sy = fadd2(fadd2(p.y, q.y), bb2);
        up2(sx, res.x, res.y);
        up2(sy, res.z, res.w);
    }
    x++;
    return res;
}

// ---------------------------------------------------------------------------
__global__ void __launch_bounds__(TPB, 1) __cluster_dims__(2, 1, 1)
odernn_kernel(const float *__restrict__ dataset,    // [B, T, OBS]
              const float *__restrict__ timestamps, // [B, T]
              const float *__restrict__ W1,  const float *__restrict__ b1,
              const float *__restrict__ W2,  const float *__restrict__ b2,
              const float *__restrict__ Wr1, const float *__restrict__ br1,
              const float *__restrict__ Wr2, const float *__restrict__ br2,
              float *__restrict__ out)               // [B, LAT]
{
    extern __shared__ char smem[];
    ulonglong2 *sC    = reinterpret_cast<ulonglong2 *>(smem);         // [320]
    ulonglong2 *sTmp  = sC + KRNN;                                    // [256]
    ulonglong2 *sHid  = sTmp + LAT;                                   // [256]
    ulonglong2 *sPart = sHid + HHALF;                                 // [8*256]
    ulonglong2 *sPeer = sPart + NSL * NC;                             // [2*256]
    float      *sH    = reinterpret_cast<float *>(sPeer + 2 * NC);    // [4]
    u64        *mbarp = reinterpret_cast<u64 *>(sH + 4);              // [1]

    const int t = threadIdx.x;
    u32 rank;
    asm("mov.u32 %0, %%cluster_ctarank;" : "=r"(rank));
    const u32 peerRank = rank ^ 1u;
    const int row0  = (blockIdx.x >> 1) * ROWS;
    const int hbase = (int)rank * HHALF;

    const int s  = t >> 7;            // K-slice 0..7
    const int c0 = 2 * (t & 127);     // 2-column group

    const u32 mbarAddr     = smem_u32(mbarp);
    const u32 mbarPeerAddr = mapa32(mbarAddr, peerRank);
    const u32 peerBufAddr  = mapa32(smem_u32(sPeer), peerRank);

    // weight slices for this rank
    const float *W1r  = W1  + hbase;                    // cols [hbase, +256)
    const float *Wr1r = Wr1 + hbase;
    const float *W2r  = W2  + (size_t)hbase * LAT;      // K-rows [hbase, +256)
    const float *Wr2r = Wr2 + (size_t)hbase * LAT;

    const float baO = (t < NC) ? b1[hbase + t]  : 0.f;
    const float baR = (t < NC) ? br1[hbase + t] : 0.f;
    const float bbO = (t < NC) ? b2[t]  : 0.f;
    const float bbR = (t < NC) ? br2[t] : 0.f;

    // ---- init: mbar, state = 0, x_{T-1} ----
    if (t == 0)
        asm volatile("mbarrier.init.shared.b64 [%0], %1;"
                     :: "r"(mbarAddr), "r"(NC) : "memory");
    if (t < LAT) store_p(&sC[t], 0.f, 0.f, 0.f, 0.f);
    if (t < LAT) {
        const int cc = t & (OBSD - 1);
        const int r  = t >> 6;     // entry = 4 floats r0..r3 in order
        float v = dataset[((row0 + r) * TSEQ + (TSEQ - 1)) * OBSD + cc];
        reinterpret_cast<float *>(&sC[LAT + cc])[r] = v;
    }
    __syncthreads();
    cluster_sync();   // mbar + state visible cluster-wide before first exchange

    int x = 0;        // exchange counter (uniform across both CTAs)

    // ---- initial RNN update: s += rnn(concat(s, x_{T-1})) ----
    {
        float4 o = mlp_eval<KRNN / NSL>(sC, Wr1r, baR, Wr2r, bbR,
                                        sHid, sPart, sPeer,
                                        peerBufAddr, mbarAddr, mbarPeerAddr,
                                        t, s, c0, x);
        if (t < NC) {
            ulonglong2 d = sC[t];
            float s0, s1, s2, s3;
            up2(d.x, s0, s1); up2(d.y, s2, s3);
            store_p(&sC[t], s0 + o.x, s1 + o.y, s2 + o.z, s3 + o.w);
        }
        __syncthreads();
    }

    // ---- reverse-time scan: i = T-2 .. 0 ----
    for (int i = TSEQ - 2; i >= 0; --i) {
        if (t < LAT) {
            const int cc = t & (OBSD - 1);
            const int r  = t >> 6;
            float v = dataset[((row0 + r) * TSEQ + i) * OBSD + cc];
            reinterpret_cast<float *>(&sC[LAT + cc])[r] = v;
        }
        if (t < ROWS) {
            const float *tsr = timestamps + (row0 + t) * TSEQ;
            sH[t] = (tsr[i] - tsr[i + 1]) / 3.0f;
        }
        __syncthreads();

        const float h0 = sH[0], h1 = sH[1], h2 = sH[2], h3 = sH[3];
        const float q0 = 0.5f * h0, q1 = 0.5f * h1, q2 = 0.5f * h2, q3 = 0.5f * h3;
        const float g0 = h0 / 6.0f, g1 = h1 / 6.0f, g2 = h2 / 6.0f, g3 = h3 / 6.0f;

#pragma unroll 1
        for (int sub = 0; sub < 3; ++sub) {
            float s0 = 0.f, s1 = 0.f, s2 = 0.f, s3 = 0.f;
            if (t < NC) {
                ulonglong2 d = sC[t];
                up2(d.x, s0, s1); up2(d.y, s2, s3);
            }
            float a0 = 0.f, a1 = 0.f, a2 = 0.f, a3 = 0.f;

            // k1
            float4 k = mlp_eval<LAT / NSL>(sC, W1r, baO, W2r, bbO,
                                           sHid, sPart, sPeer,
                                           peerBufAddr, mbarAddr, mbarPeerAddr,
                                           t, s, c0, x);
            if (t < NC) {
                a0 = k.x; a1 = k.y; a2 = k.z; a3 = k.w;
                store_p(&sTmp[t], fmaf(q0, k.x, s0), fmaf(q1, k.y, s1),
                                  fmaf(q2, k.z, s2), fmaf(q3, k.w, s3));
            }
            __syncthreads();

            // k2
            k = mlp_eval<LAT / NSL>(sTmp, W1r, baO, W2r, bbO,
                                    sHid, sPart, sPeer,
                                    peerBufAddr, mbarAddr, mbarPeerAddr,
                                    t, s, c0, x);
            if (t < NC) {
                a0 += 2.f * k.x; a1 += 2.f * k.y; a2 += 2.f * k.z; a3 += 2.f * k.w;
                store_p(&sTmp[t], fmaf(q0, k.x, s0), fmaf(q1, k.y, s1),
                                  fmaf(q2, k.z, s2), fmaf(q3, k.w, s3));
            }
            __syncthreads();

            // k3
            k = mlp_eval<LAT / NSL>(sTmp, W1r, baO, W2r, bbO,
                                    sHid, sPart, sPeer,
                                    peerBufAddr, mbarAddr, mbarPeerAddr,
                                    t, s, c0, x);
            if (t < NC) {
                a0 += 2.f * k.x; a1 += 2.f * k.y; a2 += 2.f * k.z; a3 += 2.f * k.w;
                store_p(&sTmp[t], fmaf(h0, k.x, s0), fmaf(h1, k.y, s1),
                                  fmaf(h2, k.z, s2), fmaf(h3, k.w, s3));
            }
            __syncthreads();

            // k4 + state update
            k = mlp_eval<LAT / NSL>(sTmp, W1r, baO, W2r, bbO,
                                    sHid, sPart, sPeer,
                                    peerBufAddr, mbarAddr, mbarPeerAddr,
                                    t, s, c0, x);
            if (t < NC) {
                a0 += k.x; a1 += k.y; a2 += k.z; a3 += k.w;
                store_p(&sC[t], fmaf(g0, a0, s0), fmaf(g1, a1, s1),
                                fmaf(g2, a2, s2), fmaf(g3, a3, s3));
            }
            __syncthreads();
        }

        // ---- RNN update: s += rnn(concat(s, x_i)) ----
        {
            float4 o = mlp_eval<KRNN / NSL>(sC, Wr1r, baR, Wr2r, bbR,
                                            sHid, sPart, sPeer,
                                            peerBufAddr, mbarAddr, mbarPeerAddr,
                                            t, s, c0, x);
            if (t < NC) {
                ulonglong2 d = sC[t];
                float s0, s1, s2, s3;
                up2(d.x, s0, s1); up2(d.y, s2, s3);
                store_p(&sC[t], s0 + o.x, s1 + o.y, s2 + o.z, s3 + o.w);
            }
            __syncthreads();
        }
    }

    // ---- write final state (rank 0 only) ----
    if (rank == 0 && t < NC) {
        ulonglong2 d = sC[t];
        float s0, s1, s2, s3;
        up2(d.x, s0, s1); up2(d.y, s2, s3);
        out[(row0 + 0) * LAT + t] = s0;
        out[(row0 + 1) * LAT + t] = s1;
        out[(row0 + 2) * LAT + t] = s2;
        out[(row0 + 3) * LAT + t] = s3;
    }

    cluster_sync();   // no CTA exits while peer traffic may be in flight
}

// ---------------------------------------------------------------------------
extern "C" void kernel_launch(void* const* d_in, const int* in_sizes, int n_in,
                              void* d_out, int out_size)
{
    (void)in_sizes; (void)n_in; (void)out_size;
    const float* dataset    = (const float*)d_in[0];
    const float* timestamps = (const float*)d_in[1];
    const float* W1  = (const float*)d_in[2];
    const float* b1  = (const float*)d_in[3];
    const float* W2  = (const float*)d_in[4];
    const float* b2  = (const float*)d_in[5];
    const float* Wr1 = (const float*)d_in[6];
    const float* br1 = (const float*)d_in[7];
    const float* Wr2 = (const float*)d_in[8];
    const float* br2 = (const float*)d_in[9];
    float* out = (float*)d_out;

    const size_t smem = (KRNN + LAT + HHALF) * sizeof(ulonglong2)
                      + (NSL * NC + 2 * NC) * sizeof(ulonglong2)
                      + 4 * sizeof(float) + 2 * sizeof(u64) + 64;
    static int configured = 0;
    if (!configured) {
        cudaFuncSetAttribute(odernn_kernel,
                             cudaFuncAttributeMaxDynamicSharedMemorySize,
                             (int)smem);
        configured = 1;
    }
    odernn_kernel<<<NCTA, TPB, smem>>>(dataset, timestamps,
                                       W1, b1, W2, b2, Wr1, br1, Wr2, br2, out);
}